// round 5
// baseline (speedup 1.0000x reference)
#include <cuda_runtime.h>
#include <cuda_bf16.h>
#include <cstdint>

// Problem shape: B=32, F=32, N=36, D=2048, P=512
#define MTOT  36864
#define NOBJ  36
#define DDIM  2048
#define PDIM  512
#define NBF   1024

// ---------------------------------------------------------------------------
// Scratch (allocation-free rule: __device__ globals)
// ---------------------------------------------------------------------------
__device__ float g_sig[(size_t)MTOT * PDIM];
__device__ float g_psi[(size_t)MTOT * PDIM];
__device__ float g_v  [(size_t)MTOT * PDIM];
// int8 2-limb quantized operands
__device__ int8_t g_x1[(size_t)MTOT * DDIM];
__device__ int8_t g_x2[(size_t)MTOT * DDIM];
__device__ int8_t g_w1[(size_t)4 * PDIM * DDIM];   // [proj][P][D] transposed
__device__ int8_t g_w2[(size_t)4 * PDIM * DDIM];
__device__ float  g_mx[MTOT];                      // per-row |x| max
__device__ float  g_mw[4 * PDIM];                  // per-col |w| max

// ---------------------------------------------------------------------------
// PTX helpers (plain sm_80-era instructions only)
// ---------------------------------------------------------------------------
__device__ __forceinline__ uint32_t smem_u32(const void* p) {
    uint32_t a;
    asm("{ .reg .u64 t; cvta.to.shared.u64 t, %1; cvt.u32.u64 %0, t; }" : "=r"(a) : "l"(p));
    return a;
}
__device__ __forceinline__ void cp16(uint32_t saddr, const void* g) {
    asm volatile("cp.async.ca.shared.global [%0], [%1], 16;" :: "r"(saddr), "l"(g));
}
__device__ __forceinline__ void cp_commit() {
    asm volatile("cp.async.commit_group;" ::: "memory");
}
__device__ __forceinline__ void cp_wait0() {
    asm volatile("cp.async.wait_group 0;" ::: "memory");
}
__device__ __forceinline__ void ldsm_x4(uint32_t* r, uint32_t addr) {
    asm volatile("ldmatrix.sync.aligned.m8n8.x4.shared.b16 {%0,%1,%2,%3}, [%4];"
                 : "=r"(r[0]), "=r"(r[1]), "=r"(r[2]), "=r"(r[3]) : "r"(addr));
}
// int8 IMMA: D(s32) += A(s8 16x32) * B(s8 32x8)
__device__ __forceinline__ void mma_s8(int* d, const uint32_t* a,
                                       uint32_t b0, uint32_t b1) {
    asm volatile(
        "mma.sync.aligned.m16n8k32.row.col.s32.s8.s8.s32 "
        "{%0,%1,%2,%3}, {%4,%5,%6,%7}, {%8,%9}, {%0,%1,%2,%3};"
        : "+r"(d[0]), "+r"(d[1]), "+r"(d[2]), "+r"(d[3])
        : "r"(a[0]), "r"(a[1]), "r"(a[2]), "r"(a[3]), "r"(b0), "r"(b1));
}
__device__ __forceinline__ uint32_t pack4(int a, int b, int c, int d) {
    return (uint32_t)(a & 0xff) | ((uint32_t)(b & 0xff) << 8) |
           ((uint32_t)(c & 0xff) << 16) | ((uint32_t)(d & 0xff) << 24);
}

// ---------------------------------------------------------------------------
// prep_w_max: per (proj, col) max |W|
// ---------------------------------------------------------------------------
__global__ void prep_w_max(const float* __restrict__ Wp, const float* __restrict__ Ws,
                           const float* __restrict__ Wq, const float* __restrict__ Wr)
{
    __shared__ float red[8][32];
    const float* W;
    switch (blockIdx.z) {
        case 0:  W = Wp; break;
        case 1:  W = Ws; break;
        case 2:  W = Wq; break;
        default: W = Wr; break;
    }
    const int p0 = blockIdx.x * 32;
    const int tx = threadIdx.x, ty = threadIdx.y;
    float m = 0.0f;
    for (int d = ty; d < DDIM; d += 8)
        m = fmaxf(m, fabsf(W[(size_t)d * PDIM + p0 + tx]));
    red[ty][tx] = m;
    __syncthreads();
    if (ty == 0) {
        #pragma unroll
        for (int k = 1; k < 8; k++) m = fmaxf(m, red[k][tx]);
        g_mw[blockIdx.z * PDIM + p0 + tx] = fmaxf(m, 1e-20f);
    }
}

// ---------------------------------------------------------------------------
// prep_w_quant: transpose + 2-limb int8 quantize W[D,P] -> [proj][P][D]
// ---------------------------------------------------------------------------
__global__ void prep_w_quant(const float* __restrict__ Wp, const float* __restrict__ Ws,
                             const float* __restrict__ Wq, const float* __restrict__ Wr)
{
    __shared__ float t[32][33];
    const float* W;
    switch (blockIdx.z) {
        case 0:  W = Wp; break;
        case 1:  W = Ws; break;
        case 2:  W = Wq; break;
        default: W = Wr; break;
    }
    const int p0 = blockIdx.x * 32, d0 = blockIdx.y * 32;
    const int tx = threadIdx.x, ty = threadIdx.y;
    #pragma unroll
    for (int k = 0; k < 4; k++)
        t[ty + k * 8][tx] = W[(size_t)(d0 + ty + k * 8) * PDIM + p0 + tx];
    __syncthreads();
    #pragma unroll
    for (int k = 0; k < 4; k++) {
        const int p = p0 + ty + k * 8;
        const float inv = 127.0f / g_mw[blockIdx.z * PDIM + p];
        const float v = t[tx][ty + k * 8];
        const float q  = v * inv;
        const float q1 = rintf(q);
        const float q2 = rintf((q - q1) * 128.0f);
        const size_t o = ((size_t)blockIdx.z * PDIM + p) * DDIM + d0 + tx;
        g_w1[o] = (int8_t)(int)q1;
        g_w2[o] = (int8_t)(int)q2;
    }
}

// ---------------------------------------------------------------------------
// prep_x: per-row max + 2-limb int8 quantize X (one CTA per row)
// ---------------------------------------------------------------------------
__global__ void __launch_bounds__(256) prep_x(const float* __restrict__ X)
{
    __shared__ float red[8];
    __shared__ float s_m;
    const int row = blockIdx.x, tid = threadIdx.x;
    const float* src = X + (size_t)row * DDIM + tid * 8;
    float4 u0 = *(const float4*)(src);
    float4 u1 = *(const float4*)(src + 4);
    float f[8] = {u0.x, u0.y, u0.z, u0.w, u1.x, u1.y, u1.z, u1.w};
    float m = 0.0f;
    #pragma unroll
    for (int i = 0; i < 8; i++) m = fmaxf(m, fabsf(f[i]));
    #pragma unroll
    for (int s = 16; s > 0; s >>= 1)
        m = fmaxf(m, __shfl_xor_sync(0xffffffffu, m, s));
    if ((tid & 31) == 0) red[tid >> 5] = m;
    __syncthreads();
    if (tid == 0) {
        float mm = red[0];
        #pragma unroll
        for (int k = 1; k < 8; k++) mm = fmaxf(mm, red[k]);
        mm = fmaxf(mm, 1e-20f);
        s_m = mm;
        g_mx[row] = mm;
    }
    __syncthreads();
    const float inv = 127.0f / s_m;
    int i1[8], i2[8];
    #pragma unroll
    for (int i = 0; i < 8; i++) {
        const float q  = f[i] * inv;
        const float q1 = rintf(q);
        i1[i] = (int)q1;
        i2[i] = (int)rintf((q - q1) * 128.0f);
    }
    uint2 p1, p2;
    p1.x = pack4(i1[0], i1[1], i1[2], i1[3]);
    p1.y = pack4(i1[4], i1[5], i1[6], i1[7]);
    p2.x = pack4(i2[0], i2[1], i2[2], i2[3]);
    p2.y = pack4(i2[4], i2[5], i2[6], i2[7]);
    *(uint2*)(g_x1 + (size_t)row * DDIM + tid * 8) = p1;
    *(uint2*)(g_x2 + (size_t)row * DDIM + tid * 8) = p2;
}

// ---------------------------------------------------------------------------
// int8x3 GEMM: CTA tile 128x128, BK=64 (2 x k32 steps), 8 warps (4M x 2N),
// warp tile 32x64. Passes: hh -> acc_hh, lh+hl -> acc_mid.
// C = (hh*16384 + mid*128) * m_x*m_w/16256^2 + bias.
// ---------------------------------------------------------------------------
#define BKB     64            // K bytes per chunk
#define PADB16  40            // smem row stride in b16 units (80 bytes)
#define OFF_A1  0             // 128*80 = 10240
#define OFF_A2  10240
#define OFF_B1  20480
#define OFF_B2  30720
#define STAGE   40960
#define NCHUNK  (DDIM / BKB)  // 32
#define GEMM_SMEM (2 * STAGE) // 81920

__global__ void __launch_bounds__(256, 1) gemm_kernel(
    const float* __restrict__ bp, const float* __restrict__ bs,
    const float* __restrict__ bq,
    float* __restrict__ out)
{
    extern __shared__ char smem[];
    __shared__ float s_bias[128];
    __shared__ float s_sw[128];
    const uint32_t sb = smem_u32(smem);

    const int tid  = threadIdx.x;
    const int proj = blockIdx.x >> 2;
    const int bcol = (blockIdx.x & 3) * 128;
    const int brow = blockIdx.y * 128;

    float* C;
    const float* bias;
    switch (proj) {
        case 0:  C = out;   bias = bp;      break;
        case 1:  C = g_sig; bias = bs;      break;
        case 2:  C = g_psi; bias = bq;      break;
        default: C = g_v;   bias = nullptr; break;
    }
    if (tid < 128) {
        s_bias[tid] = bias ? bias[bcol + tid] : 0.0f;
        s_sw[tid]   = g_mw[proj * PDIM + bcol + tid] * (1.0f / (16256.0f * 16256.0f));
    }

    const int lane = tid & 31, wid = tid >> 5;
    const int warp_m = (wid & 3) * 32;
    const int warp_n = (wid >> 2) * 64;

    // staging: 2 threads per 64-byte row; each does 2 cp16 per limb
    const int srow = tid >> 1;             // 0..127
    const int soff = (tid & 1) * 32;       // byte offset 0/32
    const int8_t* ax1 = g_x1 + (size_t)(brow + srow) * DDIM + soff;
    const int8_t* ax2 = g_x2 + (size_t)(brow + srow) * DDIM + soff;
    const int8_t* bw1 = g_w1 + (size_t)(proj * PDIM + bcol + srow) * DDIM + soff;
    const int8_t* bw2 = g_w2 + (size_t)(proj * PDIM + bcol + srow) * DDIM + soff;
    const uint32_t s_st = (uint32_t)(srow * 80 + soff);

    // ldmatrix per-lane pieces (b16-view addressing, identical to bf16 kernel)
    const int a_r  = warp_m + (lane & 15);
    const int a_cs = (lane >> 4) * 8;                         // b16 cols
    const int b_r  = warp_n + (lane >> 4) * 8 + (lane & 7);
    const int b_cs = ((lane >> 3) & 1) * 8;

    int acc_hh[2][8][4], acc_mid[2][8][4];
    #pragma unroll
    for (int mt = 0; mt < 2; mt++)
        #pragma unroll
        for (int n = 0; n < 8; n++)
            #pragma unroll
            for (int q = 0; q < 4; q++) { acc_hh[mt][n][q] = 0; acc_mid[mt][n][q] = 0; }

    #define ISSUE_CP(ch, st_) do { \
        const uint32_t o_ = sb + (st_) + s_st; \
        const size_t g_ = (size_t)(ch) * BKB; \
        cp16(o_ + OFF_A1,      ax1 + g_); \
        cp16(o_ + OFF_A1 + 16, ax1 + g_ + 16); \
        cp16(o_ + OFF_A2,      ax2 + g_); \
        cp16(o_ + OFF_A2 + 16, ax2 + g_ + 16); \
        cp16(o_ + OFF_B1,      bw1 + g_); \
        cp16(o_ + OFF_B1 + 16, bw1 + g_ + 16); \
        cp16(o_ + OFF_B2,      bw2 + g_); \
        cp16(o_ + OFF_B2 + 16, bw2 + g_ + 16); \
        cp_commit(); \
    } while (0)

    // prologue
    ISSUE_CP(0, 0);
    cp_wait0();
    __syncthreads();

    for (int ch = 0; ch < NCHUNK; ch++) {
        const uint32_t cur = (ch & 1) * STAGE;
        const uint32_t nxt = ((ch + 1) & 1) * STAGE;

        if (ch + 1 < NCHUNK) ISSUE_CP(ch + 1, nxt);

        const uint32_t sA1 = sb + cur + OFF_A1;
        const uint32_t sA2 = sb + cur + OFF_A2;
        const uint32_t sB1 = sb + cur + OFF_B1;
        const uint32_t sB2 = sb + cur + OFF_B2;

        #pragma unroll
        for (int ks = 0; ks < 2; ks++) {
            uint32_t a1[2][4], a2[2][4], b1[4][4], b2[4][4];
            #pragma unroll
            for (int mt = 0; mt < 2; mt++) {
                const uint32_t ao = (uint32_t)((a_r + mt * 16) * PADB16 + ks * 16 + a_cs) * 2;
                ldsm_x4(a1[mt], sA1 + ao);
                ldsm_x4(a2[mt], sA2 + ao);
            }
            #pragma unroll
            for (int ng = 0; ng < 4; ng++) {
                const uint32_t bo = (uint32_t)((b_r + ng * 16) * PADB16 + ks * 16 + b_cs) * 2;
                ldsm_x4(b1[ng], sB1 + bo);
            }
            // pass hh: a1*b1 -> acc_hh (16 independent MMAs)
            #pragma unroll
            for (int mt = 0; mt < 2; mt++)
                #pragma unroll
                for (int ng = 0; ng < 4; ng++) {
                    mma_s8(acc_hh[mt][ng * 2],     a1[mt], b1[ng][0], b1[ng][1]);
                    mma_s8(acc_hh[mt][ng * 2 + 1], a1[mt], b1[ng][2], b1[ng][3]);
                }
            // pass lh: a2*b1 -> acc_mid
            #pragma unroll
            for (int mt = 0; mt < 2; mt++)
                #pragma unroll
                for (int ng = 0; ng < 4; ng++) {
                    mma_s8(acc_mid[mt][ng * 2],     a2[mt], b1[ng][0], b1[ng][1]);
                    mma_s8(acc_mid[mt][ng * 2 + 1], a2[mt], b1[ng][2], b1[ng][3]);
                }
            #pragma unroll
            for (int ng = 0; ng < 4; ng++) {
                const uint32_t bo = (uint32_t)((b_r + ng * 16) * PADB16 + ks * 16 + b_cs) * 2;
                ldsm_x4(b2[ng], sB2 + bo);
            }
            // pass hl: a1*b2 -> acc_mid
            #pragma unroll
            for (int mt = 0; mt < 2; mt++)
                #pragma unroll
                for (int ng = 0; ng < 4; ng++) {
                    mma_s8(acc_mid[mt][ng * 2],     a1[mt], b2[ng][0], b2[ng][1]);
                    mma_s8(acc_mid[mt][ng * 2 + 1], a1[mt], b2[ng][2], b2[ng][3]);
                }
        }

        if (ch + 1 < NCHUNK) {
            cp_wait0();
            __syncthreads();
        }
    }

    // epilogue
    #pragma unroll
    for (int mt = 0; mt < 2; mt++) {
        const int r0 = brow + warp_m + mt * 16 + (lane >> 2);
        const float sx0 = g_mx[r0];
        const float sx1 = g_mx[r0 + 8];
        #pragma unroll
        for (int n8 = 0; n8 < 8; n8++) {
            const int c = warp_n + n8 * 8 + (lane & 3) * 2;
            const float w0 = s_sw[c], w1 = s_sw[c + 1];
            float f0 = (float)acc_hh[mt][n8][0] * 16384.0f + (float)acc_mid[mt][n8][0] * 128.0f;
            float f1 = (float)acc_hh[mt][n8][1] * 16384.0f + (float)acc_mid[mt][n8][1] * 128.0f;
            float f2 = (float)acc_hh[mt][n8][2] * 16384.0f + (float)acc_mid[mt][n8][2] * 128.0f;
            float f3 = (float)acc_hh[mt][n8][3] * 16384.0f + (float)acc_mid[mt][n8][3] * 128.0f;
            float2 v0, v1;
            v0.x = f0 * sx0 * w0 + s_bias[c];
            v0.y = f1 * sx0 * w1 + s_bias[c + 1];
            v1.x = f2 * sx1 * w0 + s_bias[c];
            v1.y = f3 * sx1 * w1 + s_bias[c + 1];
            *(float2*)(C + (size_t)r0 * PDIM + bcol + c)       = v0;
            *(float2*)(C + (size_t)(r0 + 8) * PDIM + bcol + c) = v1;
        }
    }
}

// ---------------------------------------------------------------------------
// Per-(b,f) attention: scores = sig @ psi^T [36x36], softmax, r_hat = A @ v.
// ---------------------------------------------------------------------------
#define RS 516
#define SC 37
#define ATTN_SMEM_FLOATS (2 * NOBJ * RS + NOBJ * SC)

__global__ void __launch_bounds__(256) attn_kernel(float* __restrict__ out)
{
    extern __shared__ float sm[];
    float* s_psi = sm;
    float* s_buf = sm + NOBJ * RS;
    float* s_sc  = sm + 2 * NOBJ * RS;

    const int bf  = blockIdx.x;
    const int tid = threadIdx.x;

    const float* sigg = g_sig + (size_t)bf * NOBJ * PDIM;
    const float* psig = g_psi + (size_t)bf * NOBJ * PDIM;
    const float* vg   = g_v   + (size_t)bf * NOBJ * PDIM;

    for (int i = tid; i < NOBJ * 128; i += 256) {
        const int n = i >> 7, p4 = (i & 127) << 2;
        *(float4*)&s_buf[n * RS + p4] = *(const float4*)&sigg[n * PDIM + p4];
        *(float4*)&s_psi[n * RS + p4] = *(const float4*)&psig[n * PDIM + p4];
    }
    __syncthreads();

    {
        const int ti = tid & 15;
        const int tj = tid >> 4;
        const bool nok2 = (tj + 32) < NOBJ;
        const bool mok2 = (ti + 32) < NOBJ;
        const int tj2 = nok2 ? tj + 32 : 0;
        const int ti2 = mok2 ? ti + 32 : 0;

        float acc[3][3];
        #pragma unroll
        for (int a = 0; a < 3; a++)
            #pragma unroll
            for (int b = 0; b < 3; b++) acc[a][b] = 0.0f;

        for (int k = 0; k < PDIM; k += 4) {
            const float4 a0 = *(const float4*)&s_buf[(tj)      * RS + k];
            const float4 a1 = *(const float4*)&s_buf[(tj + 16) * RS + k];
            const float4 a2 = *(const float4*)&s_buf[(tj2)     * RS + k];
            const float4 b0 = *(const float4*)&s_psi[(ti)      * RS + k];
            const float4 b1 = *(const float4*)&s_psi[(ti + 16) * RS + k];
            const float4 b2 = *(const float4*)&s_psi[(ti2)     * RS + k];
            acc[0][0] += a0.x*b0.x + a0.y*b0.y + a0.z*b0.z + a0.w*b0.w;
            acc[0][1] += a0.x*b1.x + a0.y*b1.y + a0.z*b1.z + a0.w*b1.w;
            acc[0][2] += a0.x*b2.x + a0.y*b2.y + a0.z*b2.z + a0.w*b2.w;
            acc[1][0] += a1.x*b0.x + a1.y*b0.y + a1.z*b0.z + a1.w*b0.w;
            acc[1][1] += a1.x*b1.x + a1.y*b1.y + a1.z*b1.z + a1.w*b1.w;
            acc[1][2] += a1.x*b2.x + a1.y*b2.y + a1.z*b2.z + a1.w*b2.w;
            acc[2][0] += a2.x*b0.x + a2.y*b0.y + a2.z*b0.z + a2.w*b0.w;
            acc[2][1] += a2.x*b1.x + a2.y*b1.y + a2.z*b1.z + a2.w*b1.w;
            acc[2][2] += a2.x*b2.x + a2.y*b2.y + a2.z*b2.z + a2.w*b2.w;
        }
        #pragma unroll
        for (int a = 0; a < 3; a++) {
            const int n = tj + 16 * a;
            if (n >= NOBJ) break;
            #pragma unroll
            for (int b = 0; b < 3; b++) {
                const int m = ti + 16 * b;
                if (m < NOBJ) s_sc[n * SC + m] = acc[a][b];
            }
        }
    }
    __syncthreads();

    if (tid < NOBJ) {
        float mx = -1e30f;
        #pragma unroll
        for (int m = 0; m < NOBJ; m++) mx = fmaxf(mx, s_sc[tid * SC + m]);
        float s = 0.0f;
        #pragma unroll
        for (int m = 0; m < NOBJ; m++) {
            const float e = __expf(s_sc[tid * SC + m] - mx);
            s_sc[tid * SC + m] = e;
            s += e;
        }
        const float inv = 1.0f / s;
        #pragma unroll
        for (int m = 0; m < NOBJ; m++) s_sc[tid * SC + m] *= inv;
    }
    __syncthreads();

    for (int i = tid; i < NOBJ * 128; i += 256) {
        const int n = i >> 7, p4 = (i & 127) << 2;
        *(float4*)&s_buf[n * RS + p4] = *(const float4*)&vg[n * PDIM + p4];
    }
    __syncthreads();

    float* rhat = out + (size_t)MTOT * PDIM + (size_t)bf * NOBJ * PDIM;
    #pragma unroll
    for (int p0 = 0; p0 < PDIM; p0 += 256) {
        const int p = p0 + tid;
        float vr[NOBJ];
        #pragma unroll
        for (int m = 0; m < NOBJ; m++) vr[m] = s_buf[m * RS + p];
        #pragma unroll 4
        for (int n = 0; n < NOBJ; n++) {
            float s = 0.0f;
            #pragma unroll
            for (int m = 0; m < NOBJ; m++)
                s = fmaf(s_sc[n * SC + m], vr[m], s);
            rhat[n * PDIM + p] = s;
        }
    }
}

// ---------------------------------------------------------------------------
extern "C" void kernel_launch(void* const* d_in, const int* in_sizes, int n_in,
                              void* d_out, int out_size)
{
    const float* X   = (const float*)d_in[0];
    const float* Wp  = (const float*)d_in[1];
    const float* bp  = (const float*)d_in[2];
    const float* Ws  = (const float*)d_in[3];
    const float* bs  = (const float*)d_in[4];
    const float* Wq  = (const float*)d_in[5];
    const float* bq  = (const float*)d_in[6];
    const float* Wr  = (const float*)d_in[7];
    float* out = (float*)d_out;

    prep_w_max<<<dim3(PDIM / 32, 1, 4), dim3(32, 8)>>>(Wp, Ws, Wq, Wr);
    prep_w_quant<<<dim3(PDIM / 32, DDIM / 32, 4), dim3(32, 8)>>>(Wp, Ws, Wq, Wr);
    prep_x<<<MTOT, 256>>>(X);

    cudaFuncSetAttribute(gemm_kernel,
                         cudaFuncAttributeMaxDynamicSharedMemorySize, GEMM_SMEM);
    gemm_kernel<<<dim3(16, MTOT / 128), 256, GEMM_SMEM>>>(bp, bs, bq, out);

    const int attn_smem = ATTN_SMEM_FLOATS * (int)sizeof(float);
    cudaFuncSetAttribute(attn_kernel,
                         cudaFuncAttributeMaxDynamicSharedMemorySize, attn_smem);
    attn_kernel<<<NBF, 256, attn_smem>>>(out);
}

// round 6
// speedup vs baseline: 2.2096x; 2.2096x over previous
#include <cuda_runtime.h>
#include <cuda_bf16.h>
#include <cstdint>

// Problem shape: B=32, F=32, N=36, D=2048, P=512
#define MTOT  36864
#define NOBJ  36
#define DDIM  2048
#define PDIM  512
#define NBF   1024

// ---------------------------------------------------------------------------
// Scratch (allocation-free rule: __device__ globals)
// ---------------------------------------------------------------------------
__device__ float g_sig[(size_t)MTOT * PDIM];
__device__ float g_psi[(size_t)MTOT * PDIM];
__device__ float g_v  [(size_t)MTOT * PDIM];
// W transposed + bf16-split: layout [proj][P][D]
__device__ __nv_bfloat16 g_wt_hi[(size_t)4 * PDIM * DDIM];
__device__ __nv_bfloat16 g_wt_lo[(size_t)4 * PDIM * DDIM];

// ---------------------------------------------------------------------------
// PTX helpers (plain sm_80-era instructions only)
// ---------------------------------------------------------------------------
__device__ __forceinline__ uint32_t smem_u32(const void* p) {
    uint32_t a;
    asm("{ .reg .u64 t; cvta.to.shared.u64 t, %1; cvt.u32.u64 %0, t; }" : "=r"(a) : "l"(p));
    return a;
}
__device__ __forceinline__ void cp16(uint32_t saddr, const void* g) {
    asm volatile("cp.async.ca.shared.global [%0], [%1], 16;" :: "r"(saddr), "l"(g));
}
__device__ __forceinline__ void cp_commit() {
    asm volatile("cp.async.commit_group;" ::: "memory");
}
__device__ __forceinline__ void cp_wait0() {
    asm volatile("cp.async.wait_group 0;" ::: "memory");
}
__device__ __forceinline__ void ldsm_x4(uint32_t* r, uint32_t addr) {
    asm volatile("ldmatrix.sync.aligned.m8n8.x4.shared.b16 {%0,%1,%2,%3}, [%4];"
                 : "=r"(r[0]), "=r"(r[1]), "=r"(r[2]), "=r"(r[3]) : "r"(addr));
}
__device__ __forceinline__ void mma_bf16(float* d, const uint32_t* a,
                                         uint32_t b0, uint32_t b1) {
    asm volatile(
        "mma.sync.aligned.m16n8k16.row.col.f32.bf16.bf16.f32 "
        "{%0,%1,%2,%3}, {%4,%5,%6,%7}, {%8,%9}, {%0,%1,%2,%3};"
        : "+f"(d[0]), "+f"(d[1]), "+f"(d[2]), "+f"(d[3])
        : "r"(a[0]), "r"(a[1]), "r"(a[2]), "r"(a[3]), "r"(b0), "r"(b1));
}
__device__ __forceinline__ uint32_t pack_bf2(__nv_bfloat16 a, __nv_bfloat16 b) {
    __nv_bfloat162 t;
    t.x = a; t.y = b;
    return *reinterpret_cast<uint32_t*>(&t);
}
__device__ __forceinline__ void cvt8(const float4 f0, const float4 f1, uint4& hu, uint4& lu) {
    float f[8] = {f0.x, f0.y, f0.z, f0.w, f1.x, f1.y, f1.z, f1.w};
    __nv_bfloat16 h[8], l[8];
    #pragma unroll
    for (int i = 0; i < 8; i++) {
        h[i] = __float2bfloat16_rn(f[i]);
        l[i] = __float2bfloat16_rn(f[i] - __bfloat162float(h[i]));
    }
    hu.x = pack_bf2(h[0], h[1]); hu.y = pack_bf2(h[2], h[3]);
    hu.z = pack_bf2(h[4], h[5]); hu.w = pack_bf2(h[6], h[7]);
    lu.x = pack_bf2(l[0], l[1]); lu.y = pack_bf2(l[2], l[3]);
    lu.z = pack_bf2(l[4], l[5]); lu.w = pack_bf2(l[6], l[7]);
}

// ---------------------------------------------------------------------------
// Prep: transpose + bf16-split W[D,P] -> Wt_{hi,lo}[proj][P][D]
// ---------------------------------------------------------------------------
__global__ void prep_kernel(const float* __restrict__ Wp, const float* __restrict__ Ws,
                            const float* __restrict__ Wq, const float* __restrict__ Wr)
{
    __shared__ float t[32][33];
    const float* W;
    switch (blockIdx.z) {
        case 0:  W = Wp; break;
        case 1:  W = Ws; break;
        case 2:  W = Wq; break;
        default: W = Wr; break;
    }
    const int p0 = blockIdx.x * 32, d0 = blockIdx.y * 32;
    const int tx = threadIdx.x, ty = threadIdx.y;
    #pragma unroll
    for (int k = 0; k < 4; k++)
        t[ty + k * 8][tx] = W[(size_t)(d0 + ty + k * 8) * PDIM + p0 + tx];
    __syncthreads();
    #pragma unroll
    for (int k = 0; k < 4; k++) {
        const int p = p0 + ty + k * 8;
        const float v = t[tx][ty + k * 8];
        __nv_bfloat16 h = __float2bfloat16_rn(v);
        __nv_bfloat16 l = __float2bfloat16_rn(v - __bfloat162float(h));
        const size_t o = ((size_t)blockIdx.z * PDIM + p) * DDIM + d0 + tx;
        g_wt_hi[o] = h;
        g_wt_lo[o] = l;
    }
}

// ---------------------------------------------------------------------------
// bf16x3 GEMM: CTA tile 128x128, BK=32, 16 warps (4M x 4N), warp tile 32x32.
// ~100 regs/thread -> no spills at the 128-reg cap. Pass-separated MMA order
// (8 independent MMAs between accumulator reuses). Double-buffered smem.
// ---------------------------------------------------------------------------
#define BK      32
#define PAD     40            // smem row stride in b16 units
#define OFF_AH  0             // 128*40*2 = 10240
#define OFF_AL  10240
#define OFF_BH  20480
#define OFF_BL  30720
#define STAGE   40960
#define NCHUNK  (DDIM / BK)   // 64
#define GEMM_SMEM (2 * STAGE) // 81920

__global__ void __launch_bounds__(512, 1) gemm_kernel(
    const float* __restrict__ X,
    const float* __restrict__ bp, const float* __restrict__ bs,
    const float* __restrict__ bq,
    float* __restrict__ out)
{
    extern __shared__ char smem[];
    __shared__ float s_bias[128];
    const uint32_t sb = smem_u32(smem);

    const int tid  = threadIdx.x;
    const int proj = blockIdx.x >> 2;
    const int bcol = (blockIdx.x & 3) * 128;
    const int brow = blockIdx.y * 128;

    float* C;
    const float* bias;
    switch (proj) {
        case 0:  C = out;   bias = bp;      break;
        case 1:  C = g_sig; bias = bs;      break;
        case 2:  C = g_psi; bias = bq;      break;
        default: C = g_v;   bias = nullptr; break;
    }
    if (tid < 128) s_bias[tid] = bias ? bias[bcol + tid] : 0.0f;

    const int lane = tid & 31, wid = tid >> 5;
    const int warp_m = (wid & 3) * 32;
    const int warp_n = (wid >> 2) * 32;

    // A staging: 128 rows x 32 fp32; 4 threads/row, 8 floats each
    const int arow = tid >> 2;
    const int acb  = (tid & 3) * 8;
    const float* aptr = X + (size_t)(brow + arow) * DDIM + acb;

    // B staging: 128 rows x 32 bf16 (per limb); 4 threads/row, 8 bf16 each
    const int bro = tid >> 2;
    const int bcb = (tid & 3) * 8;
    const __nv_bfloat16* wtH = g_wt_hi + (size_t)(proj * PDIM + bcol + bro) * DDIM + bcb;
    const __nv_bfloat16* wtL = g_wt_lo + (size_t)(proj * PDIM + bcol + bro) * DDIM + bcb;

    // ldmatrix per-lane pieces
    const int a_r  = warp_m + (lane & 15);
    const int a_cs = (lane >> 4) * 8;
    const int b_r  = warp_n + (lane >> 4) * 8 + (lane & 7);
    const int b_cs = ((lane >> 3) & 1) * 8;

    float acc[2][4][4];
    #pragma unroll
    for (int mt = 0; mt < 2; mt++)
        #pragma unroll
        for (int n = 0; n < 4; n++)
            #pragma unroll
            for (int q = 0; q < 4; q++) acc[mt][n][q] = 0.0f;

    float4 fA0, fA1;
    #define LOAD_A_REGS(ch) do { \
        const float* p_ = aptr + (ch) * BK; \
        fA0 = *(const float4*)(p_); \
        fA1 = *(const float4*)(p_ + 4); \
    } while (0)

    #define STORE_A_SMEM(st_) do { \
        uint4 h0, l0; \
        cvt8(fA0, fA1, h0, l0); \
        const uint32_t o_ = (st_) + (uint32_t)(arow * PAD + acb) * 2; \
        *(uint4*)(smem + o_ + OFF_AH) = h0; \
        *(uint4*)(smem + o_ + OFF_AL) = l0; \
    } while (0)

    #define ISSUE_B_CP(ch, st_) do { \
        const uint32_t o_ = sb + (st_) + (uint32_t)(bro * PAD + bcb) * 2; \
        cp16(o_ + OFF_BH, wtH + (ch) * BK); \
        cp16(o_ + OFF_BL, wtL + (ch) * BK); \
        cp_commit(); \
    } while (0)

    // prologue
    ISSUE_B_CP(0, 0);
    LOAD_A_REGS(0);
    STORE_A_SMEM(0u);
    cp_wait0();
    __syncthreads();

    for (int ch = 0; ch < NCHUNK; ch++) {
        const uint32_t cur = (ch & 1) * STAGE;
        const uint32_t nxt = ((ch + 1) & 1) * STAGE;

        if (ch + 1 < NCHUNK) {
            ISSUE_B_CP(ch + 1, nxt);
            LOAD_A_REGS(ch + 1);
        }

        const uint32_t sAh = sb + cur + OFF_AH;
        const uint32_t sAl = sb + cur + OFF_AL;
        const uint32_t sBh = sb + cur + OFF_BH;
        const uint32_t sBl = sb + cur + OFF_BL;

        #pragma unroll
        for (int ks = 0; ks < 2; ks++) {
            uint32_t ah[2][4], al[2][4], bh[2][4], bl[2][4];
            #pragma unroll
            for (int mt = 0; mt < 2; mt++) {
                const uint32_t ao = (uint32_t)((a_r + mt * 16) * PAD + ks * 16 + a_cs) * 2;
                ldsm_x4(ah[mt], sAh + ao);
                ldsm_x4(al[mt], sAl + ao);
            }
            #pragma unroll
            for (int ng = 0; ng < 2; ng++) {
                const uint32_t bo = (uint32_t)((b_r + ng * 16) * PAD + ks * 16 + b_cs) * 2;
                ldsm_x4(bh[ng], sBh + bo);
                ldsm_x4(bl[ng], sBl + bo);
            }
            // pass 1: hi*hi (8 independent MMAs)
            #pragma unroll
            for (int mt = 0; mt < 2; mt++)
                #pragma unroll
                for (int ng = 0; ng < 2; ng++) {
                    mma_bf16(acc[mt][ng * 2],     ah[mt], bh[ng][0], bh[ng][1]);
                    mma_bf16(acc[mt][ng * 2 + 1], ah[mt], bh[ng][2], bh[ng][3]);
                }
            // pass 2: hi*lo
            #pragma unroll
            for (int mt = 0; mt < 2; mt++)
                #pragma unroll
                for (int ng = 0; ng < 2; ng++) {
                    mma_bf16(acc[mt][ng * 2],     ah[mt], bl[ng][0], bl[ng][1]);
                    mma_bf16(acc[mt][ng * 2 + 1], ah[mt], bl[ng][2], bl[ng][3]);
                }
            // pass 3: lo*hi
            #pragma unroll
            for (int mt = 0; mt < 2; mt++)
                #pragma unroll
                for (int ng = 0; ng < 2; ng++) {
                    mma_bf16(acc[mt][ng * 2],     al[mt], bh[ng][0], bh[ng][1]);
                    mma_bf16(acc[mt][ng * 2 + 1], al[mt], bh[ng][2], bh[ng][3]);
                }
        }

        if (ch + 1 < NCHUNK) {
            STORE_A_SMEM(nxt);
            cp_wait0();
            __syncthreads();
        }
    }

    // epilogue
    #pragma unroll
    for (int mt = 0; mt < 2; mt++) {
        const int r0 = brow + warp_m + mt * 16 + (lane >> 2);
        #pragma unroll
        for (int n8 = 0; n8 < 4; n8++) {
            const int c = warp_n + n8 * 8 + (lane & 3) * 2;
            float2 v0, v1;
            v0.x = acc[mt][n8][0] + s_bias[c];
            v0.y = acc[mt][n8][1] + s_bias[c + 1];
            v1.x = acc[mt][n8][2] + s_bias[c];
            v1.y = acc[mt][n8][3] + s_bias[c + 1];
            *(float2*)(C + (size_t)r0 * PDIM + bcol + c)       = v0;
            *(float2*)(C + (size_t)(r0 + 8) * PDIM + bcol + c) = v1;
        }
    }
}

// ---------------------------------------------------------------------------
// Per-(b,f) attention, k-split staging for 2 CTAs/SM.
// scores = sig @ psi^T [36x36] (two 256-wide k-halves, partial sums in regs),
// softmax, r_hat = A @ v (two 256-wide p-halves).
// ---------------------------------------------------------------------------
#define KH  256                     // k/p half width
#define RS2 260                     // padded row stride (floats)
#define SC  37
#define ATTN_SMEM_FLOATS (2 * NOBJ * RS2 + NOBJ * SC)

__global__ void __launch_bounds__(256) attn_kernel(float* __restrict__ out)
{
    extern __shared__ float sm[];
    float* s_sig = sm;                     // [NOBJ][RS2] (later v)
    float* s_psi = sm + NOBJ * RS2;        // [NOBJ][RS2]
    float* s_sc  = sm + 2 * NOBJ * RS2;    // [NOBJ][SC]

    const int bf  = blockIdx.x;
    const int tid = threadIdx.x;

    const float* sigg = g_sig + (size_t)bf * NOBJ * PDIM;
    const float* psig = g_psi + (size_t)bf * NOBJ * PDIM;
    const float* vg   = g_v   + (size_t)bf * NOBJ * PDIM;

    const int ti = tid & 15;
    const int tj = tid >> 4;
    const bool nok2 = (tj + 32) < NOBJ;
    const bool mok2 = (ti + 32) < NOBJ;
    const int tj2 = nok2 ? tj + 32 : 0;
    const int ti2 = mok2 ? ti + 32 : 0;

    float acc[3][3];
    #pragma unroll
    for (int a = 0; a < 3; a++)
        #pragma unroll
        for (int b = 0; b < 3; b++) acc[a][b] = 0.0f;

    // ---- scores over two k-halves ----
    #pragma unroll
    for (int half = 0; half < 2; half++) {
        if (half) __syncthreads();         // protect buffer reuse
        for (int i = tid; i < NOBJ * (KH / 4); i += 256) {
            const int n = i >> 6, p4 = (i & 63) << 2;
            *(float4*)&s_sig[n * RS2 + p4] = *(const float4*)&sigg[n * PDIM + half * KH + p4];
            *(float4*)&s_psi[n * RS2 + p4] = *(const float4*)&psig[n * PDIM + half * KH + p4];
        }
        __syncthreads();

        for (int k = 0; k < KH; k += 4) {
            const float4 a0 = *(const float4*)&s_sig[(tj)      * RS2 + k];
            const float4 a1 = *(const float4*)&s_sig[(tj + 16) * RS2 + k];
            const float4 a2 = *(const float4*)&s_sig[(tj2)     * RS2 + k];
            const float4 b0 = *(const float4*)&s_psi[(ti)      * RS2 + k];
            const float4 b1 = *(const float4*)&s_psi[(ti + 16) * RS2 + k];
            const float4 b2 = *(const float4*)&s_psi[(ti2)     * RS2 + k];
            acc[0][0] += a0.x*b0.x + a0.y*b0.y + a0.z*b0.z + a0.w*b0.w;
            acc[0][1] += a0.x*b1.x + a0.y*b1.y + a0.z*b1.z + a0.w*b1.w;
            acc[0][2] += a0.x*b2.x + a0.y*b2.y + a0.z*b2.z + a0.w*b2.w;
            acc[1][0] += a1.x*b0.x + a1.y*b0.y + a1.z*b0.z + a1.w*b0.w;
            acc[1][1] += a1.x*b1.x + a1.y*b1.y + a1.z*b1.z + a1.w*b1.w;
            acc[1][2] += a1.x*b2.x + a1.y*b2.y + a1.z*b2.z + a1.w*b2.w;
            acc[2][0] += a2.x*b0.x + a2.y*b0.y + a2.z*b0.z + a2.w*b0.w;
            acc[2][1] += a2.x*b1.x + a2.y*b1.y + a2.z*b1.z + a2.w*b1.w;
            acc[2][2] += a2.x*b2.x + a2.y*b2.y + a2.z*b2.z + a2.w*b2.w;
        }
    }
    #pragma unroll
    for (int a = 0; a < 3; a++) {
        const int n = tj + 16 * a;
        if (n >= NOBJ) break;
        #pragma unroll
        for (int b = 0; b < 3; b++) {
            const int m = ti + 16 * b;
            if (m < NOBJ) s_sc[n * SC + m] = acc[a][b];
        }
    }
    __syncthreads();

    // ---- softmax (one thread per row) ----
    if (tid < NOBJ) {
        float mx = -1e30f;
        #pragma unroll
        for (int m = 0; m < NOBJ; m++) mx = fmaxf(mx, s_sc[tid * SC + m]);
        float s = 0.0f;
        #pragma unroll
        for (int m = 0; m < NOBJ; m++) {
            const float e = __expf(s_sc[tid * SC + m] - mx);
            s_sc[tid * SC + m] = e;
            s += e;
        }
        const float inv = 1.0f / s;
        #pragma unroll
        for (int m = 0; m < NOBJ; m++) s_sc[tid * SC + m] *= inv;
    }
    __syncthreads();

    // ---- r_hat = A @ v over two p-halves (reuse s_sig as v buffer) ----
    float* rhat = out + (size_t)MTOT * PDIM + (size_t)bf * NOBJ * PDIM;
    #pragma unroll
    for (int half = 0; half < 2; half++) {
        if (half) __syncthreads();
        for (int i = tid; i < NOBJ * (KH / 4); i += 256) {
            const int n = i >> 6, p4 = (i & 63) << 2;
            *(float4*)&s_sig[n * RS2 + p4] = *(const float4*)&vg[n * PDIM + half * KH + p4];
        }
        __syncthreads();

        const int p = tid;                // 256 threads, 256 cols
        float vr[NOBJ];
        #pragma unroll
        for (int m = 0; m < NOBJ; m++) vr[m] = s_sig[m * RS2 + p];
        #pragma unroll 4
        for (int n = 0; n < NOBJ; n++) {
            float s = 0.0f;
            #pragma unroll
            for (int m = 0; m < NOBJ; m++)
                s = fmaf(s_sc[n * SC + m], vr[m], s);
            rhat[n * PDIM + half * KH + p] = s;
        }
    }
}

// ---------------------------------------------------------------------------
extern "C" void kernel_launch(void* const* d_in, const int* in_sizes, int n_in,
                              void* d_out, int out_size)
{
    const float* X   = (const float*)d_in[0];
    const float* Wp  = (const float*)d_in[1];
    const float* bp  = (const float*)d_in[2];
    const float* Ws  = (const float*)d_in[3];
    const float* bs  = (const float*)d_in[4];
    const float* Wq  = (const float*)d_in[5];
    const float* bq  = (const float*)d_in[6];
    const float* Wr  = (const float*)d_in[7];
    float* out = (float*)d_out;

    prep_kernel<<<dim3(PDIM / 32, DDIM / 32, 4), dim3(32, 8)>>>(Wp, Ws, Wq, Wr);

    cudaFuncSetAttribute(gemm_kernel,
                         cudaFuncAttributeMaxDynamicSharedMemorySize, GEMM_SMEM);
    gemm_kernel<<<dim3(16, MTOT / 128), 512, GEMM_SMEM>>>(X, bp, bs, bq, out);

    const int attn_smem = ATTN_SMEM_FLOATS * (int)sizeof(float);
    cudaFuncSetAttribute(attn_kernel,
                         cudaFuncAttributeMaxDynamicSharedMemorySize, attn_smem);
    attn_kernel<<<NBF, 256, attn_smem>>>(out);
}